// round 2
// baseline (speedup 1.0000x reference)
#include <cuda_runtime.h>
#include <math.h>

#define BB 4
#define CC 64
#define OO 64
#define HH 128
#define WW 128
#define OGG 2
#define CG 32
#define KK2 9
#define OMC 54           // 36 offset + 18 mask channels
#define SP (HH*WW)       // 16384

// scratch for offset+mask conv output: [B][54][H][W]
__device__ float g_offmask[BB * OMC * HH * WW];

// ---------------------------------------------------------------------------
// Kernel 1: 3x3 conv producing 36 offset channels + 18 mask channels (sigmoid)
// Tile 16x16 pixels, input channels in chunks of 8 staged in smem.
// ---------------------------------------------------------------------------
__global__ __launch_bounds__(256) void conv_offmask_kernel(
    const float* __restrict__ x,
    const float* __restrict__ w_off, const float* __restrict__ b_off,
    const float* __restrict__ w_mask, const float* __restrict__ b_mask)
{
    __shared__ float xs[8][18][18];
    __shared__ __align__(16) float ws[8 * 9 * 56];   // [c][k][56] (54 padded to 56)

    const int tx = threadIdx.x;
    const int ty = threadIdx.y;
    const int tid = ty * 16 + tx;
    const int tileX0 = blockIdx.x * 16;
    const int tileY0 = blockIdx.y * 16;
    const int b = blockIdx.z;

    float acc[56];
#pragma unroll
    for (int i = 0; i < 56; i++) acc[i] = 0.f;

    for (int cc = 0; cc < CC; cc += 8) {
        __syncthreads();
        // stage x tile (18x18 halo) for 8 channels
        for (int i = tid; i < 8 * 18 * 18; i += 256) {
            int c = i / 324;
            int r = (i % 324) / 18;
            int col = i % 18;
            int gy = tileY0 + r - 1;
            int gx = tileX0 + col - 1;
            float v = 0.f;
            if (gy >= 0 && gy < HH && gx >= 0 && gx < WW)
                v = x[(((size_t)b * CC + cc + c) * HH + gy) * WW + gx];
            xs[c][r][col] = v;
        }
        // stage weights for 8 channels: ws[(c*9+k)*56 + o]
        for (int i = tid; i < 8 * 9 * 56; i += 256) {
            int c = i / (9 * 56);
            int k = (i / 56) % 9;
            int o = i % 56;
            float v = 0.f;
            if (o < 36)       v = w_off[(size_t)o * (CC * 9) + (cc + c) * 9 + k];
            else if (o < 54)  v = w_mask[(size_t)(o - 36) * (CC * 9) + (cc + c) * 9 + k];
            ws[i] = v;
        }
        __syncthreads();

#pragma unroll 1
        for (int c = 0; c < 8; c++) {
#pragma unroll
            for (int k = 0; k < 9; k++) {
                float xv = xs[c][ty + k / 3][tx + k % 3];
                const float4* wp = (const float4*)&ws[(c * 9 + k) * 56];
#pragma unroll
                for (int j = 0; j < 14; j++) {
                    float4 w4 = wp[j];
                    acc[4 * j + 0] += xv * w4.x;
                    acc[4 * j + 1] += xv * w4.y;
                    acc[4 * j + 2] += xv * w4.z;
                    acc[4 * j + 3] += xv * w4.w;
                }
            }
        }
    }

    const int y = tileY0 + ty;
    const int xcol = tileX0 + tx;
    float* outbase = g_offmask + ((size_t)b * OMC) * SP + y * WW + xcol;
#pragma unroll 1
    for (int o = 0; o < 54; o++) {
        float bias = (o < 36) ? b_off[o] : b_mask[o - 36];
        float v = acc[o] + bias;
        if (o >= 36) v = 1.f / (1.f + expf(-v));
        outbase[(size_t)o * SP] = v;
    }
}

// ---------------------------------------------------------------------------
// Kernel 2: deformable conv. One pixel per thread, 64 fp32 accumulators.
// Full main weight (64x64x9 = 147456 B) in dynamic smem, layout [(c*9+k)][64].
// ---------------------------------------------------------------------------
__global__ __launch_bounds__(256, 1) void deform_kernel(
    const float* __restrict__ x,
    const float* __restrict__ w_main,
    float* __restrict__ out)
{
    extern __shared__ __align__(16) float wsm[];   // [(c*9+k)*64 + o]
    const int tid = threadIdx.x;

    // stage all weights: wsm[ck*64 + o] = w_main[o*576 + ck]
    for (int i = tid; i < OO * CC * KK2; i += 256) {
        int o = i & 63;
        int ck = i >> 6;
        wsm[i] = w_main[(size_t)o * (CC * KK2) + ck];
    }
    __syncthreads();

    const int p = blockIdx.x * 256 + tid;   // 0 .. B*H*W-1
    const int b = p / SP;
    const int rem = p % SP;
    const int y = rem / WW;
    const int xc = rem % WW;

    float acc[64];
#pragma unroll
    for (int i = 0; i < 64; i++) acc[i] = 0.f;

    const float* offp = g_offmask + ((size_t)b * OMC) * SP + y * WW + xc;
    const float* xb_batch = x + ((size_t)b * CC) * SP;

#pragma unroll 1
    for (int g = 0; g < OGG; g++) {
#pragma unroll 1
        for (int k = 0; k < KK2; k++) {
            float oy = offp[(size_t)(g * 18 + k * 2 + 0) * SP];
            float ox = offp[(size_t)(g * 18 + k * 2 + 1) * SP];
            float m  = offp[(size_t)(36 + g * 9 + k) * SP];

            float py = oy + (float)(y - 1 + k / 3);
            float px = ox + (float)(xc - 1 + k % 3);
            float y0f = floorf(py);
            float x0f = floorf(px);
            float wy1 = py - y0f;
            float wx1 = px - x0f;
            float wy0 = 1.f - wy1;
            float wx0 = 1.f - wx1;
            int y0 = (int)y0f;
            int x0 = (int)x0f;
            int y1 = y0 + 1;
            int x1 = x0 + 1;
            float vy0 = (y0 >= 0 && y0 < HH) ? 1.f : 0.f;
            float vy1 = (y1 >= 0 && y1 < HH) ? 1.f : 0.f;
            float vx0 = (x0 >= 0 && x0 < WW) ? 1.f : 0.f;
            float vx1 = (x1 >= 0 && x1 < WW) ? 1.f : 0.f;
            int y0c = min(max(y0, 0), HH - 1);
            int y1c = min(max(y1, 0), HH - 1);
            int x0c = min(max(x0, 0), WW - 1);
            int x1c = min(max(x1, 0), WW - 1);

            float w00 = wy0 * wx0 * vy0 * vx0 * m;
            float w01 = wy0 * wx1 * vy0 * vx1 * m;
            float w10 = wy1 * wx0 * vy1 * vx0 * m;
            float w11 = wy1 * wx1 * vy1 * vx1 * m;

            int i00 = y0c * WW + x0c;
            int i01 = y0c * WW + x1c;
            int i10 = y1c * WW + x0c;
            int i11 = y1c * WW + x1c;

            const float* xg = xb_batch + (size_t)(g * CG) * SP;
            const float4* wbase = (const float4*)&wsm[((size_t)(g * CG) * KK2 + k) * 64];

#pragma unroll 2
            for (int c = 0; c < CG; c++) {
                const float* xch = xg + (size_t)c * SP;
                float v = w00 * xch[i00] + w01 * xch[i01]
                        + w10 * xch[i10] + w11 * xch[i11];
                const float4* wp = wbase + c * (KK2 * 16);
#pragma unroll
                for (int j = 0; j < 16; j++) {
                    float4 w4 = wp[j];
                    acc[4 * j + 0] += v * w4.x;
                    acc[4 * j + 1] += v * w4.y;
                    acc[4 * j + 2] += v * w4.z;
                    acc[4 * j + 3] += v * w4.w;
                }
            }
        }
    }

    float* outp = out + ((size_t)b * OO) * SP + y * WW + xc;
#pragma unroll 1
    for (int o = 0; o < 64; o++)
        outp[(size_t)o * SP] = acc[o];
}

// ---------------------------------------------------------------------------
extern "C" void kernel_launch(void* const* d_in, const int* in_sizes, int n_in,
                              void* d_out, int out_size)
{
    (void)in_sizes; (void)n_in; (void)out_size;
    const float* x      = (const float*)d_in[0];
    const float* w_main = (const float*)d_in[1];
    const float* w_off  = (const float*)d_in[2];
    const float* b_off  = (const float*)d_in[3];
    const float* w_mask = (const float*)d_in[4];
    const float* b_mask = (const float*)d_in[5];
    float* out = (float*)d_out;

    static bool attr_set = false;
    if (!attr_set) {
        cudaFuncSetAttribute(deform_kernel,
                             cudaFuncAttributeMaxDynamicSharedMemorySize,
                             OO * CC * KK2 * (int)sizeof(float));
        attr_set = true;
    }

    dim3 grid1(WW / 16, HH / 16, BB);
    dim3 blk1(16, 16);
    conv_offmask_kernel<<<grid1, blk1>>>(x, w_off, b_off, w_mask, b_mask);

    int nPix = BB * HH * WW;
    deform_kernel<<<nPix / 256, 256, OO * CC * KK2 * (int)sizeof(float)>>>(
        x, w_main, out);
}

// round 4
// speedup vs baseline: 1.8840x; 1.8840x over previous
#include <cuda_runtime.h>
#include <math.h>

#define BB 4
#define CC 64
#define OO 64
#define HH 128
#define WW 128
#define OGG 2
#define CG 32
#define KK2 9
#define OMC 54           // 36 offset + 18 mask channels
#define SP (HH*WW)       // 16384

// scratch for offset+mask conv output: [B][54][H][W]
__device__ float g_offmask[BB * OMC * HH * WW];

// ---------------------------------------------------------------------------
// Kernel 1: 3x3 conv producing 36 offset channels + 18 mask channels (sigmoid)
// Tile 16x16 pixels, input channels in chunks of 8 staged in smem.
// ---------------------------------------------------------------------------
__global__ __launch_bounds__(256) void conv_offmask_kernel(
    const float* __restrict__ x,
    const float* __restrict__ w_off, const float* __restrict__ b_off,
    const float* __restrict__ w_mask, const float* __restrict__ b_mask)
{
    __shared__ float xs[8][18][18];
    __shared__ __align__(16) float ws[8 * 9 * 56];   // [c][k][56] (54 padded to 56)

    const int tx = threadIdx.x;
    const int ty = threadIdx.y;
    const int tid = ty * 16 + tx;
    const int tileX0 = blockIdx.x * 16;
    const int tileY0 = blockIdx.y * 16;
    const int b = blockIdx.z;

    float acc[56];
#pragma unroll
    for (int i = 0; i < 56; i++) acc[i] = 0.f;

    for (int cc = 0; cc < CC; cc += 8) {
        __syncthreads();
        // stage x tile (18x18 halo) for 8 channels
        for (int i = tid; i < 8 * 18 * 18; i += 256) {
            int c = i / 324;
            int r = (i % 324) / 18;
            int col = i % 18;
            int gy = tileY0 + r - 1;
            int gx = tileX0 + col - 1;
            float v = 0.f;
            if (gy >= 0 && gy < HH && gx >= 0 && gx < WW)
                v = x[(((size_t)b * CC + cc + c) * HH + gy) * WW + gx];
            xs[c][r][col] = v;
        }
        // stage weights for 8 channels: ws[(c*9+k)*56 + o]
        for (int i = tid; i < 8 * 9 * 56; i += 256) {
            int c = i / (9 * 56);
            int k = (i / 56) % 9;
            int o = i % 56;
            float v = 0.f;
            if (o < 36)       v = w_off[(size_t)o * (CC * 9) + (cc + c) * 9 + k];
            else if (o < 54)  v = w_mask[(size_t)(o - 36) * (CC * 9) + (cc + c) * 9 + k];
            ws[i] = v;
        }
        __syncthreads();

#pragma unroll 1
        for (int c = 0; c < 8; c++) {
#pragma unroll
            for (int k = 0; k < 9; k++) {
                float xv = xs[c][ty + k / 3][tx + k % 3];
                const float4* wp = (const float4*)&ws[(c * 9 + k) * 56];
#pragma unroll
                for (int j = 0; j < 14; j++) {
                    float4 w4 = wp[j];
                    acc[4 * j + 0] += xv * w4.x;
                    acc[4 * j + 1] += xv * w4.y;
                    acc[4 * j + 2] += xv * w4.z;
                    acc[4 * j + 3] += xv * w4.w;
                }
            }
        }
    }

    const int y = tileY0 + ty;
    const int xcol = tileX0 + tx;
    float* outbase = g_offmask + ((size_t)b * OMC) * SP + y * WW + xcol;
#pragma unroll 1
    for (int o = 0; o < 54; o++) {
        float bias = (o < 36) ? b_off[o] : b_mask[o - 36];
        float v = acc[o] + bias;
        if (o >= 36) v = 1.f / (1.f + __expf(-v));
        outbase[(size_t)o * SP] = v;
    }
}

// ---------------------------------------------------------------------------
// Kernel 2: deformable conv. One pixel per thread, 64 fp32 accumulators.
// 512 threads/CTA, grid=128 (single wave), full weights (147 KB) in smem.
// Channel loop in chunks of 4 -> 16 independent LDGs batched for MLP.
// ---------------------------------------------------------------------------
__global__ __launch_bounds__(512, 1) void deform_kernel(
    const float* __restrict__ x,
    const float* __restrict__ w_main,
    float* __restrict__ out)
{
    extern __shared__ __align__(16) float wsm[];   // [(c*9+k)*64 + o]
    const int tid = threadIdx.x;

    // stage all weights: wsm[ck*64 + o] = w_main[o*576 + ck]
    for (int i = tid; i < OO * CC * KK2; i += 512) {
        int o = i & 63;
        int ck = i >> 6;
        wsm[i] = w_main[(size_t)o * (CC * KK2) + ck];
    }
    __syncthreads();

    const int p = blockIdx.x * 512 + tid;   // 0 .. B*H*W-1 (exact)
    const int b = p / SP;
    const int rem = p % SP;
    const int y = rem / WW;
    const int xc = rem % WW;

    float acc[64];
#pragma unroll
    for (int i = 0; i < 64; i++) acc[i] = 0.f;

    const float* offp = g_offmask + ((size_t)b * OMC) * SP + y * WW + xc;
    const float* xb_batch = x + ((size_t)b * CC) * SP;

#pragma unroll 1
    for (int g = 0; g < OGG; g++) {
#pragma unroll 1
        for (int k = 0; k < KK2; k++) {
            float oy = offp[(size_t)(g * 18 + k * 2 + 0) * SP];
            float ox = offp[(size_t)(g * 18 + k * 2 + 1) * SP];
            float m  = offp[(size_t)(36 + g * 9 + k) * SP];

            float py = oy + (float)(y - 1 + k / 3);
            float px = ox + (float)(xc - 1 + k % 3);
            float y0f = floorf(py);
            float x0f = floorf(px);
            float wy1 = py - y0f;
            float wx1 = px - x0f;
            float wy0 = 1.f - wy1;
            float wx0 = 1.f - wx1;
            int y0 = (int)y0f;
            int x0 = (int)x0f;
            int y1 = y0 + 1;
            int x1 = x0 + 1;
            float vy0 = (y0 >= 0 && y0 < HH) ? 1.f : 0.f;
            float vy1 = (y1 >= 0 && y1 < HH) ? 1.f : 0.f;
            float vx0 = (x0 >= 0 && x0 < WW) ? 1.f : 0.f;
            float vx1 = (x1 >= 0 && x1 < WW) ? 1.f : 0.f;
            int y0c = min(max(y0, 0), HH - 1);
            int y1c = min(max(y1, 0), HH - 1);
            int x0c = min(max(x0, 0), WW - 1);
            int x1c = min(max(x1, 0), WW - 1);

            float w00 = wy0 * wx0 * vy0 * vx0 * m;
            float w01 = wy0 * wx1 * vy0 * vx1 * m;
            float w10 = wy1 * wx0 * vy1 * vx0 * m;
            float w11 = wy1 * wx1 * vy1 * vx1 * m;

            // corner base pointers for this (g,k)
            const float* xg  = xb_batch + (size_t)(g * CG) * SP;
            const float* p00 = xg + y0c * WW + x0c;
            const float* p01 = xg + y0c * WW + x1c;
            const float* p10 = xg + y1c * WW + x0c;
            const float* p11 = xg + y1c * WW + x1c;

            const float4* wbase = (const float4*)&wsm[((size_t)(g * CG) * KK2 + k) * 64];

#pragma unroll
            for (int cc = 0; cc < CG; cc += 4) {
                // 16 independent loads batched for MLP
                float a0[4], a1[4], a2[4], a3[4];
#pragma unroll
                for (int j = 0; j < 4; j++) {
                    int coff = (cc + j) * SP;
                    a0[j] = p00[coff];
                    a1[j] = p01[coff];
                    a2[j] = p10[coff];
                    a3[j] = p11[coff];
                }
#pragma unroll
                for (int j = 0; j < 4; j++) {
                    float v = w00 * a0[j] + w01 * a1[j]
                            + w10 * a2[j] + w11 * a3[j];
                    const float4* wp = wbase + (cc + j) * (KK2 * 16);
#pragma unroll
                    for (int q = 0; q < 16; q++) {
                        float4 w4 = wp[q];
                        acc[4 * q + 0] += v * w4.x;
                        acc[4 * q + 1] += v * w4.y;
                        acc[4 * q + 2] += v * w4.z;
                        acc[4 * q + 3] += v * w4.w;
                    }
                }
            }
        }
    }

    float* outp = out + ((size_t)b * OO) * SP + y * WW + xc;
#pragma unroll 1
    for (int o = 0; o < 64; o++)
        outp[(size_t)o * SP] = acc[o];
}

// ---------------------------------------------------------------------------
extern "C" void kernel_launch(void* const* d_in, const int* in_sizes, int n_in,
                              void* d_out, int out_size)
{
    (void)in_sizes; (void)n_in; (void)out_size;
    const float* x      = (const float*)d_in[0];
    const float* w_main = (const float*)d_in[1];
    const float* w_off  = (const float*)d_in[2];
    const float* b_off  = (const float*)d_in[3];
    const float* w_mask = (const float*)d_in[4];
    const float* b_mask = (const float*)d_in[5];
    float* out = (float*)d_out;

    static bool attr_set = false;
    if (!attr_set) {
        cudaFuncSetAttribute(deform_kernel,
                             cudaFuncAttributeMaxDynamicSharedMemorySize,
                             OO * CC * KK2 * (int)sizeof(float));
        attr_set = true;
    }

    dim3 grid1(WW / 16, HH / 16, BB);
    dim3 blk1(16, 16);
    conv_offmask_kernel<<<grid1, blk1>>>(x, w_off, b_off, w_mask, b_mask);

    int nPix = BB * HH * WW;
    deform_kernel<<<nPix / 512, 512, OO * CC * KK2 * (int)sizeof(float)>>>(
        x, w_main, out);
}